// round 1
// baseline (speedup 1.0000x reference)
#include <cuda_runtime.h>
#include <math.h>

#define CHW   196608   // 3*256*256
#define NTOT  393216   // 2*CHW
#define NPERC 2097152  // 2*256*64*64
#define RAD   0.085f
#define INV255 (1.0f/255.0f)

// ---------------- scratch (static device globals; no allocs allowed) ----------------
__device__ float g_bufA[8388608];   // 2*64*256*256 floats (33.5 MB) - ping
__device__ float g_bufB[8388608];   // pong
__device__ float g_featT[2097152];  // final features of y_true
__device__ double g_acc[8];         // 0 sl1, 1 mse, 2 st0, 3 st1, 4 sp0, 5 sp1, 6 perc, 7 hist
__device__ double g_S[2];           // hist normalizers S_true, S_pred

__global__ void init_k() {
    int t = threadIdx.x;
    if (t < 8) g_acc[t] = 0.0;
    if (t < 2) g_S[t] = 0.0;
}

__device__ __forceinline__ float block_reduce(float v) {
    __shared__ float sb[8];
    #pragma unroll
    for (int o = 16; o; o >>= 1) v += __shfl_down_sync(0xffffffffu, v, o);
    if ((threadIdx.x & 31) == 0) sb[threadIdx.x >> 5] = v;
    __syncthreads();
    float r = 0.f;
    if (threadIdx.x < 8) {
        r = sb[threadIdx.x];
        #pragma unroll
        for (int o = 4; o; o >>= 1) r += __shfl_down_sync(0xffu, r, o);
    }
    __syncthreads();
    return r;   // valid in thread 0
}

// ---------------- elementwise losses: smooth-L1, MSE, per-batch sums ----------------
__global__ void elemloss_k(const float* __restrict__ yt, const float* __restrict__ yp) {
    float sl1 = 0.f, mse = 0.f, st0 = 0.f, st1 = 0.f, sp0 = 0.f, sp1 = 0.f;
    int stride = gridDim.x * blockDim.x;
    for (int i = blockIdx.x * blockDim.x + threadIdx.x; i < NTOT; i += stride) {
        float t = yt[i], p = yp[i];
        float d = p - t, ad = fabsf(d);
        sl1 += (ad < 1.f) ? 0.5f * d * d : ad - 0.5f;
        mse += d * d;
        if (i < CHW) { st0 += t; sp0 += p; } else { st1 += t; sp1 += p; }
    }
    sl1 = block_reduce(sl1); mse = block_reduce(mse);
    st0 = block_reduce(st0); st1 = block_reduce(st1);
    sp0 = block_reduce(sp0); sp1 = block_reduce(sp1);
    if (threadIdx.x == 0) {
        atomicAdd(&g_acc[0], (double)sl1); atomicAdd(&g_acc[1], (double)mse);
        atomicAdd(&g_acc[2], (double)st0); atomicAdd(&g_acc[3], (double)st1);
        atomicAdd(&g_acc[4], (double)sp0); atomicAdd(&g_acc[5], (double)sp1);
    }
}

// ---------------- soft histogram ----------------
// g(x) = sum_j exp(-0.5*((x - j/255)/0.01)^2); truncated where exponent < -36.
__device__ __forceinline__ float gsum(float v) {
    int jlo = max(0, (int)ceilf((v - RAD) * 255.f));
    int jhi = min(255, (int)floorf((v + RAD) * 255.f));
    float s = 0.f;
    for (int j = jlo; j <= jhi; ++j) {
        float t = (v - (float)j * INV255) * 100.f;
        s += __expf(-0.5f * t * t);
    }
    return s;
}

__global__ void histsum_k(const float* __restrict__ yt, const float* __restrict__ yp) {
    float st = 0.f, sp = 0.f;
    int stride = gridDim.x * blockDim.x;
    for (int i = blockIdx.x * blockDim.x + threadIdx.x; i < NTOT; i += stride) {
        st += gsum(yt[i]);
        sp += gsum(yp[i]);
    }
    st = block_reduce(st); sp = block_reduce(sp);
    if (threadIdx.x == 0) {
        atomicAdd(&g_S[0], (double)st);
        atomicAdd(&g_S[1], (double)sp);
    }
}

__device__ __forceinline__ float expw(float x, float e) {
    float d = (x - e) * 100.f;
    float a = -0.5f * d * d;
    return (a > -40.f) ? __expf(a) : 0.f;
}

// one thread per (c,h,w); h[c,h,w,bin] = k(x[0],bin)+k(x[1],bin)
__global__ void histdiff_k(const float* __restrict__ yt, const float* __restrict__ yp) {
    int idx = blockIdx.x * blockDim.x + threadIdx.x;  // grid sized to exactly CHW
    float t0 = yt[idx], t1 = yt[idx + CHW];
    float p0 = yp[idx], p1 = yp[idx + CHW];
    float invSt = (float)(1.0 / g_S[0]);
    float invSp = (float)(1.0 / g_S[1]);
    float vmin = fminf(fminf(t0, t1), fminf(p0, p1));
    float vmax = fmaxf(fmaxf(t0, t1), fmaxf(p0, p1));
    int jlo = max(0, (int)ceilf((vmin - RAD) * 255.f));
    int jhi = min(255, (int)floorf((vmax + RAD) * 255.f));
    float s = 0.f;
    for (int j = jlo; j <= jhi; ++j) {
        float e = (float)j * INV255;
        float ht = expw(t0, e) + expw(t1, e);
        float hp = expw(p0, e) + expw(p1, e);
        s += fabsf(ht * invSt - hp * invSp);
    }
    s = block_reduce(s);
    if (threadIdx.x == 0) atomicAdd(&g_acc[7], (double)s);
}

// ---------------- 3x3 SAME conv + bias + relu (direct, smem-tiled) ----------------
// block: 256 threads = 32x8; tile = 32x32 output pixels x 8 output channels.
// each thread: 4 pixels (stride 8 in y) x 8 channels = 32 accumulators.
template<int CIC>
__global__ void __launch_bounds__(256, 2) conv3x3_relu_k(
    const float* __restrict__ in, const float* __restrict__ wgt,
    const float* __restrict__ bias, float* __restrict__ out,
    int CI, int CO, int H, int W)
{
    __shared__ __align__(16) float s_in[CIC][34][34];
    __shared__ __align__(16) float s_w[CIC][9][8];
    const int tid = threadIdx.x;
    const int tx = tid & 31, ty = tid >> 5;
    const int ox0 = blockIdx.x << 5, oy0 = blockIdx.y << 5;
    const int nco = CO >> 3;
    const int co0 = (blockIdx.z % nco) << 3;
    const int n   = blockIdx.z / nco;
    const float* inN = in + (size_t)n * CI * H * W;

    float acc[4][8];
    #pragma unroll
    for (int p = 0; p < 4; ++p)
        #pragma unroll
        for (int c = 0; c < 8; ++c) acc[p][c] = 0.f;

    for (int ci0 = 0; ci0 < CI; ci0 += CIC) {
        // load input tile (with zero halo)
        for (int i = tid; i < CIC * 34 * 34; i += 256) {
            int ci = i / (34 * 34);
            int rem = i - ci * (34 * 34);
            int r = rem / 34, c = rem - r * 34;
            int iy = oy0 + r - 1, ix = ox0 + c - 1;
            float v = 0.f;
            if ((unsigned)iy < (unsigned)H && (unsigned)ix < (unsigned)W)
                v = inN[(size_t)(ci0 + ci) * H * W + (size_t)iy * W + ix];
            s_in[ci][r][c] = v;
        }
        // load weights [ci][tap][co]
        for (int i = tid; i < CIC * 72; i += 256) {
            int co = i & 7;
            int tap = (i >> 3) % 9;
            int ci = i / 72;
            s_w[ci][tap][co] = wgt[((size_t)(co0 + co) * CI + (ci0 + ci)) * 9 + tap];
        }
        __syncthreads();

        #pragma unroll 1
        for (int ci = 0; ci < CIC; ++ci) {
            #pragma unroll
            for (int ky = 0; ky < 3; ++ky) {
                #pragma unroll
                for (int kx = 0; kx < 3; ++kx) {
                    float wv[8];
                    *(float4*)(wv)     = *(const float4*)&s_w[ci][ky * 3 + kx][0];
                    *(float4*)(wv + 4) = *(const float4*)&s_w[ci][ky * 3 + kx][4];
                    #pragma unroll
                    for (int p = 0; p < 4; ++p) {
                        float iv = s_in[ci][ty + p * 8 + ky][tx + kx];
                        #pragma unroll
                        for (int c = 0; c < 8; ++c)
                            acc[p][c] = fmaf(iv, wv[c], acc[p][c]);
                    }
                }
            }
        }
        __syncthreads();
    }

    #pragma unroll
    for (int c = 0; c < 8; ++c) {
        float bv = bias[co0 + c];
        #pragma unroll
        for (int p = 0; p < 4; ++p) {
            int oy = oy0 + ty + p * 8;
            out[(((size_t)n * CO + co0 + c) * H + oy) * W + ox0 + tx] =
                fmaxf(acc[p][c] + bv, 0.f);
        }
    }
}

// ---------------- 2x2 max pool ----------------
__global__ void pool2_k(const float* __restrict__ in, float* __restrict__ out,
                        int NC, int Ho, int Wo) {
    int idx = blockIdx.x * blockDim.x + threadIdx.x;
    int total = NC * Ho * Wo;
    if (idx >= total) return;
    int x = idx % Wo;
    int y = (idx / Wo) % Ho;
    int c = idx / (Wo * Ho);
    const float* p = in + ((size_t)c * 2 * Ho + 2 * y) * (2 * Wo) + 2 * x;
    out[idx] = fmaxf(fmaxf(p[0], p[1]), fmaxf(p[2 * Wo], p[2 * Wo + 1]));
}

// ---------------- sum of squared differences (perceptual) ----------------
__global__ void sqdiff_k(const float* __restrict__ a, const float* __restrict__ b, int n) {
    float s = 0.f;
    int stride = gridDim.x * blockDim.x;
    for (int i = blockIdx.x * blockDim.x + threadIdx.x; i < n; i += stride) {
        float d = a[i] - b[i];
        s += d * d;
    }
    s = block_reduce(s);
    if (threadIdx.x == 0) atomicAdd(&g_acc[6], (double)s);
}

// ---------------- final combine ----------------
__global__ void final_k(float* out) {
    double sl1  = g_acc[0] / (double)NTOT;
    double mse  = g_acc[1] / (double)NTOT;
    double mt0  = g_acc[2] / (double)CHW, mt1 = g_acc[3] / (double)CHW;
    double mp0  = g_acc[4] / (double)CHW, mp1 = g_acc[5] / (double)CHW;
    double perc = g_acc[6] / (double)NPERC;
    double hist = g_acc[7] / 50331648.0;   // 3*256*256*256
    double psnr_l = 40.0 + 10.0 * log10(mse);
    double color  = 0.5 * (fabs(mt0 - mp0) + fabs(mt1 - mp1));
    out[0] = (float)(1.0 * sl1 + 0.06 * perc + 0.05 * hist + 0.0083 * psnr_l + 0.25 * color);
}

// ---------------- host side ----------------
static void conv_launch(const float* in, const float* w, const float* b, float* out,
                        int CI, int CO, int H, int W) {
    dim3 grid(W / 32, H / 32, 2 * (CO / 8));
    if (CI == 3)
        conv3x3_relu_k<3><<<grid, 256>>>(in, w, b, out, CI, CO, H, W);
    else
        conv3x3_relu_k<8><<<grid, 256>>>(in, w, b, out, CI, CO, H, W);
}

static void run_vgg(const float* x, const float* const* W, const float* const* B,
                    float* A, float* Bf, float* dst) {
    conv_launch(x,  W[0], B[0], A,  3,   64,  256, 256);
    conv_launch(A,  W[1], B[1], Bf, 64,  64,  256, 256);
    pool2_k<<<(2 * 64 * 128 * 128 + 255) / 256, 256>>>(Bf, A, 2 * 64, 128, 128);
    conv_launch(A,  W[2], B[2], Bf, 64,  128, 128, 128);
    conv_launch(Bf, W[3], B[3], A,  128, 128, 128, 128);
    pool2_k<<<(2 * 128 * 64 * 64 + 255) / 256, 256>>>(A, Bf, 2 * 128, 64, 64);
    conv_launch(Bf, W[4], B[4], A,  128, 256, 64, 64);
    conv_launch(A,  W[5], B[5], Bf, 256, 256, 64, 64);
    conv_launch(Bf, W[6], B[6], dst, 256, 256, 64, 64);
}

extern "C" void kernel_launch(void* const* d_in, const int* in_sizes, int n_in,
                              void* d_out, int out_size) {
    const float* yt = (const float*)d_in[0];
    const float* yp = (const float*)d_in[1];
    const float* W[7];
    const float* B[7];
    for (int i = 0; i < 7; ++i) {
        W[i] = (const float*)d_in[2 + 2 * i];
        B[i] = (const float*)d_in[3 + 2 * i];
    }
    float *bufA, *bufB, *featT;
    cudaGetSymbolAddress((void**)&bufA, g_bufA);
    cudaGetSymbolAddress((void**)&bufB, g_bufB);
    cudaGetSymbolAddress((void**)&featT, g_featT);

    init_k<<<1, 32>>>();
    elemloss_k<<<768, 256>>>(yt, yp);
    histsum_k<<<768, 256>>>(yt, yp);
    histdiff_k<<<CHW / 256, 256>>>(yt, yp);   // reads g_S (stream-ordered)

    run_vgg(yt, W, B, bufA, bufB, featT);
    run_vgg(yp, W, B, bufA, bufB, bufA);      // L7 reads bufB, writes bufA (safe)

    sqdiff_k<<<2048, 256>>>(featT, bufA, NPERC);
    final_k<<<1, 1>>>((float*)d_out);
}

// round 8
// speedup vs baseline: 6.8630x; 6.8630x over previous
#include <cuda_runtime.h>
#include <cuda_bf16.h>
#include <math.h>
#include <stdint.h>

#define CHW   196608   // 3*256*256
#define NTOT  393216   // 2*CHW
#define NPERC 2097152  // 2*256*64*64
#define RAD   0.085f
#define INV255 (1.0f/255.0f)

// ---------------- scratch ----------------
__device__ __align__(16) __nv_bfloat16 g_actA[8388608];   // NHWC ping
__device__ __align__(16) __nv_bfloat16 g_actB[8388608];   // pong
__device__ __align__(16) __nv_bfloat16 g_featT[2097152];  // net1 final features
__device__ __align__(16) __nv_bfloat16 g_wbf[1769472];    // bf16 weights [tap][co_pad][ci]
__device__ double g_acc[8];   // 0 sl1, 1 mse, 2 st0, 3 st1, 4 sp0, 5 sp1, 6 perc, 7 hist
__device__ double g_S[2];

// ================= helpers =================
__device__ __forceinline__ uint32_t smem_u32(const void* p) {
    uint32_t a;
    asm("{ .reg .u64 t; cvta.to.shared.u64 t, %1; cvt.u32.u64 %0, t; }" : "=r"(a) : "l"(p));
    return a;
}
static __device__ __forceinline__ uint32_t SW128(uint32_t off) { return off ^ ((off >> 3) & 0x70); }

__device__ __forceinline__ void cp16(uint32_t dst, const void* src, uint32_t sz) {
    asm volatile("cp.async.cg.shared.global [%0], [%1], 16, %2;"
                 :: "r"(dst), "l"(src), "r"(sz) : "memory");
}
__device__ __forceinline__ void ldx4(uint32_t* r, uint32_t addr) {
    asm volatile("ldmatrix.sync.aligned.m8n8.x4.shared.b16 {%0,%1,%2,%3}, [%4];"
        : "=r"(r[0]), "=r"(r[1]), "=r"(r[2]), "=r"(r[3]) : "r"(addr));
}
__device__ __forceinline__ void mma16816(float* d, const uint32_t* a, const uint32_t* b) {
    asm volatile("mma.sync.aligned.m16n8k16.row.col.f32.bf16.bf16.f32 "
        "{%0,%1,%2,%3}, {%4,%5,%6,%7}, {%8,%9}, {%0,%1,%2,%3};"
        : "+f"(d[0]), "+f"(d[1]), "+f"(d[2]), "+f"(d[3])
        : "r"(a[0]), "r"(a[1]), "r"(a[2]), "r"(a[3]), "r"(b[0]), "r"(b[1]));
}

// ================= small reductions =================
__global__ void init_k() {
    int t = threadIdx.x;
    if (t < 8) g_acc[t] = 0.0;
    if (t < 2) g_S[t] = 0.0;
}

__device__ __forceinline__ float block_reduce(float v) {
    __shared__ float sb[8];
    #pragma unroll
    for (int o = 16; o; o >>= 1) v += __shfl_down_sync(0xffffffffu, v, o);
    if ((threadIdx.x & 31) == 0) sb[threadIdx.x >> 5] = v;
    __syncthreads();
    float r = 0.f;
    if (threadIdx.x < 8) {
        r = sb[threadIdx.x];
        #pragma unroll
        for (int o = 4; o; o >>= 1) r += __shfl_down_sync(0xffu, r, o);
    }
    __syncthreads();
    return r;
}

__global__ void elemloss_k(const float* __restrict__ yt, const float* __restrict__ yp) {
    float sl1 = 0.f, mse = 0.f, st0 = 0.f, st1 = 0.f, sp0 = 0.f, sp1 = 0.f;
    int stride = gridDim.x * blockDim.x;
    for (int i = blockIdx.x * blockDim.x + threadIdx.x; i < NTOT; i += stride) {
        float t = yt[i], p = yp[i];
        float d = p - t, ad = fabsf(d);
        sl1 += (ad < 1.f) ? 0.5f * d * d : ad - 0.5f;
        mse += d * d;
        if (i < CHW) { st0 += t; sp0 += p; } else { st1 += t; sp1 += p; }
    }
    sl1 = block_reduce(sl1); mse = block_reduce(mse);
    st0 = block_reduce(st0); st1 = block_reduce(st1);
    sp0 = block_reduce(sp0); sp1 = block_reduce(sp1);
    if (threadIdx.x == 0) {
        atomicAdd(&g_acc[0], (double)sl1); atomicAdd(&g_acc[1], (double)mse);
        atomicAdd(&g_acc[2], (double)st0); atomicAdd(&g_acc[3], (double)st1);
        atomicAdd(&g_acc[4], (double)sp0); atomicAdd(&g_acc[5], (double)sp1);
    }
}

__device__ __forceinline__ float gsum(float v) {
    int jlo = max(0, (int)ceilf((v - RAD) * 255.f));
    int jhi = min(255, (int)floorf((v + RAD) * 255.f));
    float s = 0.f;
    for (int j = jlo; j <= jhi; ++j) {
        float t = (v - (float)j * INV255) * 100.f;
        s += __expf(-0.5f * t * t);
    }
    return s;
}

__global__ void histsum_k(const float* __restrict__ yt, const float* __restrict__ yp) {
    float st = 0.f, sp = 0.f;
    int stride = gridDim.x * blockDim.x;
    for (int i = blockIdx.x * blockDim.x + threadIdx.x; i < NTOT; i += stride) {
        st += gsum(yt[i]);
        sp += gsum(yp[i]);
    }
    st = block_reduce(st); sp = block_reduce(sp);
    if (threadIdx.x == 0) {
        atomicAdd(&g_S[0], (double)st);
        atomicAdd(&g_S[1], (double)sp);
    }
}

__device__ __forceinline__ float expw(float x, float e) {
    float d = (x - e) * 100.f;
    float a = -0.5f * d * d;
    return (a > -40.f) ? __expf(a) : 0.f;
}

__global__ void histdiff_k(const float* __restrict__ yt, const float* __restrict__ yp) {
    int idx = blockIdx.x * blockDim.x + threadIdx.x;
    float t0 = yt[idx], t1 = yt[idx + CHW];
    float p0 = yp[idx], p1 = yp[idx + CHW];
    float invSt = (float)(1.0 / g_S[0]);
    float invSp = (float)(1.0 / g_S[1]);
    float vmin = fminf(fminf(t0, t1), fminf(p0, p1));
    float vmax = fmaxf(fmaxf(t0, t1), fmaxf(p0, p1));
    int jlo = max(0, (int)ceilf((vmin - RAD) * 255.f));
    int jhi = min(255, (int)floorf((vmax + RAD) * 255.f));
    float s = 0.f;
    for (int j = jlo; j <= jhi; ++j) {
        float e = (float)j * INV255;
        float ht = expw(t0, e) + expw(t1, e);
        float hp = expw(p0, e) + expw(p1, e);
        s += fabsf(ht * invSt - hp * invSp);
    }
    s = block_reduce(s);
    if (threadIdx.x == 0) atomicAdd(&g_acc[7], (double)s);
}

// ================= weight prep: w[co][ci][3][3] f32 -> wbf[tap][co_pad][ci] bf16 =================
__global__ void wprep_k(const float* __restrict__ w, __nv_bfloat16* __restrict__ dst,
                        int COp, int COr, int CI) {
    int idx = blockIdx.x * blockDim.x + threadIdx.x;
    int total = 9 * COp * CI;
    if (idx >= total) return;
    int tap = idx / (COp * CI);
    int r = idx - tap * (COp * CI);
    int co = r / CI, ci = r - co * CI;
    float v = (co < COr) ? w[(co * CI + ci) * 9 + tap] : 0.f;
    dst[idx] = __float2bfloat16(v);
}

// ================= conv1_1: NCHW f32 (3ch) -> NHWC bf16 (64ch) + relu =================
__global__ void __launch_bounds__(256) conv1_k(
    const float* __restrict__ in, const float* __restrict__ w,
    const float* __restrict__ b, __nv_bfloat16* __restrict__ out)
{
    __shared__ float sw[1728];
    __shared__ float sb[64];
    int tid = threadIdx.x;
    for (int i = tid; i < 1728; i += 256) sw[i] = w[i];
    if (tid < 64) sb[tid] = b[tid];
    __syncthreads();

    int q = blockIdx.x * 256 + tid;
    int p4 = q * 4;
    int img = p4 >> 16;
    int rem = p4 & 65535;
    int y = rem >> 8, x = rem & 255;

    float iv[3][3][6];
    #pragma unroll
    for (int ci = 0; ci < 3; ++ci)
        #pragma unroll
        for (int r = 0; r < 3; ++r)
            #pragma unroll
            for (int c = 0; c < 6; ++c) {
                int sy = y + r - 1, sx = x + c - 1;
                float v = 0.f;
                if ((unsigned)sy < 256u && (unsigned)sx < 256u)
                    v = in[((img * 3 + ci) << 16) + (sy << 8) + sx];
                iv[ci][r][c] = v;
            }

    for (int co = 0; co < 64; ++co) {
        float a0 = sb[co], a1 = a0, a2 = a0, a3 = a0;
        #pragma unroll
        for (int ci = 0; ci < 3; ++ci)
            #pragma unroll
            for (int ky = 0; ky < 3; ++ky)
                #pragma unroll
                for (int kx = 0; kx < 3; ++kx) {
                    float wv = sw[(co * 3 + ci) * 9 + ky * 3 + kx];
                    a0 = fmaf(iv[ci][ky][kx],     wv, a0);
                    a1 = fmaf(iv[ci][ky][kx + 1], wv, a1);
                    a2 = fmaf(iv[ci][ky][kx + 2], wv, a2);
                    a3 = fmaf(iv[ci][ky][kx + 3], wv, a3);
                }
        out[(size_t)(p4 + 0) * 64 + co] = __float2bfloat16(fmaxf(a0, 0.f));
        out[(size_t)(p4 + 1) * 64 + co] = __float2bfloat16(fmaxf(a1, 0.f));
        out[(size_t)(p4 + 2) * 64 + co] = __float2bfloat16(fmaxf(a2, 0.f));
        out[(size_t)(p4 + 3) * 64 + co] = __float2bfloat16(fmaxf(a3, 0.f));
    }
}

// ================= HMMA implicit-GEMM 3x3 conv (NHWC bf16) =================
// Block tile: M=128 pixels x N=128 out-channels, K-chunk=64 ci (one SW128 row).
// 8 warps in 4(M) x 2(N); warp tile 32 pix x 64 co = 2 x 8 m16n8k16 fragments.
// Double-buffered smem stages via cp.async: stage = A(16KB pix x ci) + B(16KB co x ci).
#define STAGE_BYTES 32768
#define SMEM_TOTAL  65536

__device__ __forceinline__ void load_stage(
    uint32_t sstage, const __nv_bfloat16* __restrict__ in,
    const __nv_bfloat16* __restrict__ wbf, int it, int nc, int COp, int co0,
    int pix0, int CI, int H, int W, int lgW, int lgHW, int tid)
{
    int tap = it / nc;
    int cic = it - tap * nc;
    int dy = tap / 3 - 1, dx = tap % 3 - 1;
    const __nv_bfloat16* wt = wbf + (size_t)(tap * COp + co0) * CI + (cic << 6);
    #pragma unroll
    for (int j = 0; j < 4; ++j) {
        int id = tid + (j << 8);
        int row = id >> 3, c16 = id & 7;
        uint32_t soff = SW128((row << 7) + (c16 << 4));
        // B tile: weights [co0+row][ci chunk]
        cp16(sstage + 16384 + soff, wt + (size_t)row * CI + (c16 << 3), 16);
        // A tile: im2col activations for pixel pix0+row shifted by (dy,dx)
        int gp = pix0 + row;
        int img = gp >> lgHW;
        int p = gp & ((1 << lgHW) - 1);
        int y = p >> lgW, x = p & (W - 1);
        int sy = y + dy, sx = x + dx;
        const void* src = in;
        uint32_t sz = 0;
        if ((unsigned)sy < (unsigned)H && (unsigned)sx < (unsigned)W) {
            src = in + (size_t)((img << lgHW) + (sy << lgW) + sx) * CI + (cic << 6) + (c16 << 3);
            sz = 16;
        }
        cp16(sstage + soff, src, sz);
    }
    asm volatile("cp.async.commit_group;" ::: "memory");
}

__global__ void __launch_bounds__(256) mma_conv_k(
    const __nv_bfloat16* __restrict__ in, const __nv_bfloat16* __restrict__ wbf,
    const float* __restrict__ bias, __nv_bfloat16* __restrict__ out,
    int CI, int COr, int COp, int H, int W, int lgW, int lgHW)
{
    extern __shared__ __align__(1024) char smem[];
    uint32_t sbase = smem_u32(smem);
    const int tid = threadIdx.x;
    const int wid = tid >> 5, lane = tid & 31;
    const int warp_m = wid & 3, warp_n = wid >> 2;
    const int co0 = blockIdx.y << 7;
    const int pix0 = blockIdx.x << 7;
    const int nc = CI >> 6;
    const int ITERS = 9 * nc;

    // per-lane ldmatrix addressing (byte offsets within tile, SW128 applied later)
    const uint32_t rA = (warp_m << 5) + (lane & 15);     // A row (pixel)
    const uint32_t cA = (lane >> 4) << 4;                // A k-half byte offset
    const int t = lane >> 3;
    const uint32_t rB = (warp_n << 6) + ((t >> 1) << 3) + (lane & 7);  // B row (co)
    const uint32_t cB = (t & 1) << 4;                    // B k-half byte offset

    float acc[2][8][4];
    #pragma unroll
    for (int mt = 0; mt < 2; ++mt)
        #pragma unroll
        for (int nt = 0; nt < 8; ++nt)
            #pragma unroll
            for (int k = 0; k < 4; ++k) acc[mt][nt][k] = 0.f;

    load_stage(sbase, in, wbf, 0, nc, COp, co0, pix0, CI, H, W, lgW, lgHW, tid);

    for (int it = 0; it < ITERS; ++it) {
        if (it + 1 < ITERS) {
            load_stage(sbase + ((it + 1) & 1) * STAGE_BYTES, in, wbf, it + 1,
                       nc, COp, co0, pix0, CI, H, W, lgW, lgHW, tid);
            asm volatile("cp.async.wait_group 1;" ::: "memory");
        } else {
            asm volatile("cp.async.wait_group 0;" ::: "memory");
        }
        __syncthreads();

        uint32_t sA = sbase + (it & 1) * STAGE_BYTES;
        uint32_t sB = sA + 16384;
        #pragma unroll
        for (int ks = 0; ks < 4; ++ks) {
            uint32_t a[2][4];
            #pragma unroll
            for (int mt = 0; mt < 2; ++mt)
                ldx4(a[mt], sA + SW128(((rA + mt * 16) << 7) + ks * 32 + cA));
            uint32_t b[8][2];
            #pragma unroll
            for (int np = 0; np < 4; ++np) {
                uint32_t r4[4];
                ldx4(r4, sB + SW128(((rB + np * 16) << 7) + ks * 32 + cB));
                b[2 * np][0] = r4[0]; b[2 * np][1] = r4[1];
                b[2 * np + 1][0] = r4[2]; b[2 * np + 1][1] = r4[3];
            }
            #pragma unroll
            for (int mt = 0; mt < 2; ++mt)
                #pragma unroll
                for (int nt = 0; nt < 8; ++nt)
                    mma16816(acc[mt][nt], a[mt], b[nt]);
        }
        __syncthreads();
    }

    // epilogue: d layout — rows (lane>>2, +8), cols (lane&3)*2, +1
    const int gid = lane >> 2, tc = lane & 3;
    #pragma unroll
    for (int nt = 0; nt < 8; ++nt) {
        int co = co0 + (warp_n << 6) + nt * 8 + tc * 2;
        if (co >= COr) continue;
        float bv0 = bias[co], bv1 = bias[co + 1];
        #pragma unroll
        for (int mt = 0; mt < 2; ++mt) {
            int pix = pix0 + (warp_m << 5) + mt * 16 + gid;
            __nv_bfloat162 h0, h1;
            h0.x = __float2bfloat16(fmaxf(acc[mt][nt][0] + bv0, 0.f));
            h0.y = __float2bfloat16(fmaxf(acc[mt][nt][1] + bv1, 0.f));
            h1.x = __float2bfloat16(fmaxf(acc[mt][nt][2] + bv0, 0.f));
            h1.y = __float2bfloat16(fmaxf(acc[mt][nt][3] + bv1, 0.f));
            *(__nv_bfloat162*)(out + (size_t)pix * COr + co) = h0;
            *(__nv_bfloat162*)(out + (size_t)(pix + 8) * COr + co) = h1;
        }
    }
}

// ================= 2x2 maxpool, NHWC bf16 =================
__global__ void pool_k(const __nv_bfloat16* __restrict__ in, __nv_bfloat16* __restrict__ out,
                       int C, int Ho, int Wo) {
    int idx = blockIdx.x * blockDim.x + threadIdx.x;
    int total = 2 * Ho * Wo * C;
    if (idx >= total) return;
    int c = idx % C;
    int t = idx / C;
    int x = t % Wo; t /= Wo;
    int y = t % Ho; int img = t / Ho;
    size_t base = ((size_t)(img * 2 * Ho + 2 * y) * (2 * Wo) + 2 * x) * C + c;
    size_t rstride = (size_t)(2 * Wo) * C;
    float v0 = __bfloat162float(in[base]);
    float v1 = __bfloat162float(in[base + C]);
    float v2 = __bfloat162float(in[base + rstride]);
    float v3 = __bfloat162float(in[base + rstride + C]);
    out[idx] = __float2bfloat16(fmaxf(fmaxf(v0, v1), fmaxf(v2, v3)));
}

// ================= perceptual sum of squared diffs =================
__global__ void sqdiffb_k(const __nv_bfloat16* __restrict__ a, const __nv_bfloat16* __restrict__ b) {
    float s = 0.f;
    int stride = gridDim.x * blockDim.x;
    int nv = NPERC / 8;
    for (int i = blockIdx.x * blockDim.x + threadIdx.x; i < nv; i += stride) {
        uint4 va = *(const uint4*)(a + (size_t)i * 8);
        uint4 vb = *(const uint4*)(b + (size_t)i * 8);
        const __nv_bfloat16* pa = (const __nv_bfloat16*)&va;
        const __nv_bfloat16* pb = (const __nv_bfloat16*)&vb;
        #pragma unroll
        for (int j = 0; j < 8; ++j) {
            float d = __bfloat162float(pa[j]) - __bfloat162float(pb[j]);
            s += d * d;
        }
    }
    s = block_reduce(s);
    if (threadIdx.x == 0) atomicAdd(&g_acc[6], (double)s);
}

// ================= final combine =================
__global__ void final_k(float* out) {
    double sl1  = g_acc[0] / (double)NTOT;
    double mse  = g_acc[1] / (double)NTOT;
    double mt0  = g_acc[2] / (double)CHW, mt1 = g_acc[3] / (double)CHW;
    double mp0  = g_acc[4] / (double)CHW, mp1 = g_acc[5] / (double)CHW;
    double perc = g_acc[6] / (double)NPERC;
    double hist = g_acc[7] / 50331648.0;
    double psnr_l = 40.0 + 10.0 * log10(mse);
    double color  = 0.5 * (fabs(mt0 - mp0) + fabs(mt1 - mp1));
    out[0] = (float)(1.0 * sl1 + 0.06 * perc + 0.05 * hist + 0.0083 * psnr_l + 0.25 * color);
}

// ================= host side =================
struct LayerCfg { int woff; int CI, COr, COp, H, W, lgW, lgHW, gx, gy; };
// layers: conv1_2, conv2_1, conv2_2, conv3_1, conv3_2, conv3_3
static const LayerCfg LAY[6] = {
    {      0,  64,  64, 128, 256, 256, 8, 16, 1024, 1},
    {  73728,  64, 128, 128, 128, 128, 7, 14,  256, 1},
    { 147456, 128, 128, 128, 128, 128, 7, 14,  256, 1},
    { 294912, 128, 256, 256,  64,  64, 6, 12,   64, 2},
    { 589824, 256, 256, 256,  64,  64, 6, 12,   64, 2},
    {1179648, 256, 256, 256,  64,  64, 6, 12,   64, 2},
};

static void conv_l(int l, const __nv_bfloat16* in, const __nv_bfloat16* wbf,
                   const float* bias, __nv_bfloat16* out) {
    const LayerCfg& L = LAY[l];
    mma_conv_k<<<dim3(L.gx, L.gy), 256, SMEM_TOTAL>>>(in, wbf + L.woff, bias, out,
        L.CI, L.COr, L.COp, L.H, L.W, L.lgW, L.lgHW);
}

static void run_net(const float* x, const float* w1, const float* b1,
                    const float* const* B, __nv_bfloat16* bufA, __nv_bfloat16* bufB,
                    __nv_bfloat16* wbf, __nv_bfloat16* dst) {
    conv1_k<<<128, 256>>>(x, w1, b1, bufA);
    conv_l(0, bufA, wbf, B[0], bufB);
    pool_k<<<(2 * 128 * 128 * 64 + 255) / 256, 256>>>(bufB, bufA, 64, 128, 128);
    conv_l(1, bufA, wbf, B[1], bufB);
    conv_l(2, bufB, wbf, B[2], bufA);
    pool_k<<<(2 * 64 * 64 * 128 + 255) / 256, 256>>>(bufA, bufB, 128, 64, 64);
    conv_l(3, bufB, wbf, B[3], bufA);
    conv_l(4, bufA, wbf, B[4], bufB);
    conv_l(5, bufB, wbf, B[5], dst);
}

extern "C" void kernel_launch(void* const* d_in, const int* in_sizes, int n_in,
                              void* d_out, int out_size) {
    const float* yt = (const float*)d_in[0];
    const float* yp = (const float*)d_in[1];
    const float* W[7];
    const float* B[7];
    for (int i = 0; i < 7; ++i) {
        W[i] = (const float*)d_in[2 + 2 * i];
        B[i] = (const float*)d_in[3 + 2 * i];
    }
    __nv_bfloat16 *bufA, *bufB, *featT, *wbf;
    cudaGetSymbolAddress((void**)&bufA, g_actA);
    cudaGetSymbolAddress((void**)&bufB, g_actB);
    cudaGetSymbolAddress((void**)&featT, g_featT);
    cudaGetSymbolAddress((void**)&wbf, g_wbf);

    cudaFuncSetAttribute(mma_conv_k, cudaFuncAttributeMaxDynamicSharedMemorySize, SMEM_TOTAL);

    init_k<<<1, 32>>>();
    elemloss_k<<<768, 256>>>(yt, yp);
    histsum_k<<<768, 256>>>(yt, yp);
    histdiff_k<<<CHW / 256, 256>>>(yt, yp);

    for (int l = 0; l < 6; ++l) {
        int total = 9 * LAY[l].COp * LAY[l].CI;
        wprep_k<<<(total + 255) / 256, 256>>>(W[l + 1], wbf + LAY[l].woff,
                                              LAY[l].COp, LAY[l].COr, LAY[l].CI);
    }

    const float* Bm[6] = {B[1], B[2], B[3], B[4], B[5], B[6]};
    run_net(yt, W[0], B[0], Bm, bufA, bufB, wbf, featT);
    run_net(yp, W[0], B[0], Bm, bufA, bufB, wbf, bufA);

    sqdiffb_k<<<1024, 256>>>(featT, bufA);
    final_k<<<1, 1>>>((float*)d_out);
}

// round 10
// speedup vs baseline: 7.6645x; 1.1168x over previous
#include <cuda_runtime.h>
#include <cuda_bf16.h>
#include <math.h>
#include <stdint.h>

#define CHW   196608   // 3*256*256
#define NTOT  393216   // 2*CHW
#define NPERC 2097152  // 2*256*64*64
#define RAD   0.085f
#define INV255 (1.0f/255.0f)
#define GSUM_C 6.3919021002f   // sqrt(2*pi)*sigma/delta = 2.5066282746*2.55

// ---------------- scratch ----------------
__device__ __align__(16) __nv_bfloat16 g_actA[16777216];  // 32 MB NHWC ping (4 images)
__device__ __align__(16) __nv_bfloat16 g_actB[16777216];  // pong
__device__ __align__(16) __nv_bfloat16 g_wbf[1769472];    // bf16 weights [tap][co_pad][ci]
__device__ double g_acc[8];   // 0 sl1, 1 mse, 2 st0, 3 st1, 4 sp0, 5 sp1, 6 perc, 7 histmin
__device__ double g_S[2];

// ================= helpers =================
__device__ __forceinline__ uint32_t smem_u32(const void* p) {
    uint32_t a;
    asm("{ .reg .u64 t; cvta.to.shared.u64 t, %1; cvt.u32.u64 %0, t; }" : "=r"(a) : "l"(p));
    return a;
}
static __device__ __forceinline__ uint32_t SW128(uint32_t off) { return off ^ ((off >> 3) & 0x70); }

__device__ __forceinline__ void cp16(uint32_t dst, const void* src, uint32_t sz) {
    asm volatile("cp.async.cg.shared.global [%0], [%1], 16, %2;"
                 :: "r"(dst), "l"(src), "r"(sz) : "memory");
}
__device__ __forceinline__ void ldx4(uint32_t* r, uint32_t addr) {
    asm volatile("ldmatrix.sync.aligned.m8n8.x4.shared.b16 {%0,%1,%2,%3}, [%4];"
        : "=r"(r[0]), "=r"(r[1]), "=r"(r[2]), "=r"(r[3]) : "r"(addr));
}
__device__ __forceinline__ void mma16816(float* d, const uint32_t* a, const uint32_t* b) {
    asm volatile("mma.sync.aligned.m16n8k16.row.col.f32.bf16.bf16.f32 "
        "{%0,%1,%2,%3}, {%4,%5,%6,%7}, {%8,%9}, {%0,%1,%2,%3};"
        : "+f"(d[0]), "+f"(d[1]), "+f"(d[2]), "+f"(d[3])
        : "r"(a[0]), "r"(a[1]), "r"(a[2]), "r"(a[3]), "r"(b[0]), "r"(b[1]));
}

// ================= reductions =================
__global__ void init_k() {
    int t = threadIdx.x;
    if (t < 8) g_acc[t] = 0.0;
    if (t < 2) g_S[t] = 0.0;
}

__device__ __forceinline__ float block_reduce(float v) {
    __shared__ float sb[8];
    #pragma unroll
    for (int o = 16; o; o >>= 1) v += __shfl_down_sync(0xffffffffu, v, o);
    if ((threadIdx.x & 31) == 0) sb[threadIdx.x >> 5] = v;
    __syncthreads();
    float r = 0.f;
    if (threadIdx.x < 8) {
        r = sb[threadIdx.x];
        #pragma unroll
        for (int o = 4; o; o >>= 1) r += __shfl_down_sync(0xffu, r, o);
    }
    __syncthreads();
    return r;
}

// gsum: exact for interior via Poisson summation (fluctuation ~1e-56); explicit near edges.
__device__ __forceinline__ float gsum(float v) {
    if (v >= RAD && v <= 1.f - RAD) return GSUM_C;
    int jlo = max(0, (int)ceilf((v - RAD) * 255.f));
    int jhi = min(255, (int)floorf((v + RAD) * 255.f));
    float s = 0.f;
    for (int j = jlo; j <= jhi; ++j) {
        float t = (v - (float)j * INV255) * 100.f;
        s += __expf(-0.5f * t * t);
    }
    return s;
}

// merged pass: smooth-l1, mse, per-image sums, hist normalizers
__global__ void loss_k(const float* __restrict__ yt, const float* __restrict__ yp) {
    float sl1 = 0.f, mse = 0.f, st0 = 0.f, st1 = 0.f, sp0 = 0.f, sp1 = 0.f;
    float gt = 0.f, gp = 0.f;
    int stride = gridDim.x * blockDim.x;
    for (int i = blockIdx.x * blockDim.x + threadIdx.x; i < NTOT; i += stride) {
        float t = yt[i], p = yp[i];
        float d = p - t, ad = fabsf(d);
        sl1 += (ad < 1.f) ? 0.5f * d * d : ad - 0.5f;
        mse += d * d;
        if (i < CHW) { st0 += t; sp0 += p; } else { st1 += t; sp1 += p; }
        gt += gsum(t);
        gp += gsum(p);
    }
    sl1 = block_reduce(sl1); mse = block_reduce(mse);
    st0 = block_reduce(st0); st1 = block_reduce(st1);
    sp0 = block_reduce(sp0); sp1 = block_reduce(sp1);
    gt = block_reduce(gt);   gp = block_reduce(gp);
    if (threadIdx.x == 0) {
        atomicAdd(&g_acc[0], (double)sl1); atomicAdd(&g_acc[1], (double)mse);
        atomicAdd(&g_acc[2], (double)st0); atomicAdd(&g_acc[3], (double)st1);
        atomicAdd(&g_acc[4], (double)sp0); atomicAdd(&g_acc[5], (double)sp1);
        atomicAdd(&g_S[0], (double)gt);    atomicAdd(&g_S[1], (double)gp);
    }
}

// hist L1 via min-decomposition: sum|A-B| = 2 - 2*sum min(A,B); min nonzero only on
// the intersection of the t-window and p-window.
__global__ void histmin_k(const float* __restrict__ yt, const float* __restrict__ yp) {
    int idx = blockIdx.x * blockDim.x + threadIdx.x;  // grid = CHW/256
    float t0 = yt[idx], t1 = yt[idx + CHW];
    float p0 = yp[idx], p1 = yp[idx + CHW];
    float invSt = (float)(1.0 / g_S[0]);
    float invSp = (float)(1.0 / g_S[1]);
    int jloT = max(0, (int)ceilf((fminf(t0, t1) - RAD) * 255.f));
    int jhiT = min(255, (int)floorf((fmaxf(t0, t1) + RAD) * 255.f));
    int jloP = max(0, (int)ceilf((fminf(p0, p1) - RAD) * 255.f));
    int jhiP = min(255, (int)floorf((fmaxf(p0, p1) + RAD) * 255.f));
    int jlo = max(jloT, jloP), jhi = min(jhiT, jhiP);
    float s = 0.f;
    if (jlo <= jhi) {
        float e0 = (float)jlo * INV255;
        float u0 = (t0 - e0) * 100.f, u1 = (t1 - e0) * 100.f;
        float v0 = (p0 - e0) * 100.f, v1 = (p1 - e0) * 100.f;
        const float du = 100.f * INV255;
        for (int j = jlo; j <= jhi; ++j) {
            float ht = 0.f, hp = 0.f;
            if (fabsf(u0) < 8.6f) ht += __expf(-0.5f * u0 * u0);
            if (fabsf(u1) < 8.6f) ht += __expf(-0.5f * u1 * u1);
            if (fabsf(v0) < 8.6f) hp += __expf(-0.5f * v0 * v0);
            if (fabsf(v1) < 8.6f) hp += __expf(-0.5f * v1 * v1);
            s += fminf(ht * invSt, hp * invSp);
            u0 -= du; u1 -= du; v0 -= du; v1 -= du;
        }
    }
    s = block_reduce(s);
    if (threadIdx.x == 0) atomicAdd(&g_acc[7], (double)s);
}

// ================= weight prep =================
__global__ void wprep_k(const float* __restrict__ w, __nv_bfloat16* __restrict__ dst,
                        int COp, int COr, int CI) {
    int idx = blockIdx.x * blockDim.x + threadIdx.x;
    int total = 9 * COp * CI;
    if (idx >= total) return;
    int tap = idx / (COp * CI);
    int r = idx - tap * (COp * CI);
    int co = r / CI, ci = r - co * CI;
    float v = (co < COr) ? w[(co * CI + ci) * 9 + tap] : 0.f;
    dst[idx] = __float2bfloat16(v);
}

// ================= conv1_1: batched 4 imgs, NCHW f32 (3ch) -> NHWC bf16 (64ch) =================
__global__ void __launch_bounds__(256) conv1_k(
    const float* __restrict__ int_, const float* __restrict__ inp_,
    const float* __restrict__ w, const float* __restrict__ b,
    __nv_bfloat16* __restrict__ out)
{
    __shared__ float sw[1728];
    __shared__ float sb[64];
    int tid = threadIdx.x;
    for (int i = tid; i < 1728; i += 256) sw[i] = w[i];
    if (tid < 64) sb[tid] = b[tid];
    __syncthreads();

    int q = blockIdx.x * 256 + tid;
    int p4 = q * 4;
    int img = p4 >> 16;                 // 0..3: {t0,t1,p0,p1}
    int rem = p4 & 65535;
    int y = rem >> 8, x = rem & 255;
    const float* in = (img < 2) ? int_ : inp_;
    int li = img & 1;

    float iv[3][3][6];
    #pragma unroll
    for (int ci = 0; ci < 3; ++ci)
        #pragma unroll
        for (int r = 0; r < 3; ++r)
            #pragma unroll
            for (int c = 0; c < 6; ++c) {
                int sy = y + r - 1, sx = x + c - 1;
                float v = 0.f;
                if ((unsigned)sy < 256u && (unsigned)sx < 256u)
                    v = in[((li * 3 + ci) << 16) + (sy << 8) + sx];
                iv[ci][r][c] = v;
            }

    for (int co = 0; co < 64; ++co) {
        float a0 = sb[co], a1 = a0, a2 = a0, a3 = a0;
        #pragma unroll
        for (int ci = 0; ci < 3; ++ci)
            #pragma unroll
            for (int ky = 0; ky < 3; ++ky)
                #pragma unroll
                for (int kx = 0; kx < 3; ++kx) {
                    float wv = sw[(co * 3 + ci) * 9 + ky * 3 + kx];
                    a0 = fmaf(iv[ci][ky][kx],     wv, a0);
                    a1 = fmaf(iv[ci][ky][kx + 1], wv, a1);
                    a2 = fmaf(iv[ci][ky][kx + 2], wv, a2);
                    a3 = fmaf(iv[ci][ky][kx + 3], wv, a3);
                }
        out[(size_t)(p4 + 0) * 64 + co] = __float2bfloat16(fmaxf(a0, 0.f));
        out[(size_t)(p4 + 1) * 64 + co] = __float2bfloat16(fmaxf(a1, 0.f));
        out[(size_t)(p4 + 2) * 64 + co] = __float2bfloat16(fmaxf(a2, 0.f));
        out[(size_t)(p4 + 3) * 64 + co] = __float2bfloat16(fmaxf(a3, 0.f));
    }
}

// ================= HMMA implicit-GEMM 3x3 conv (NHWC bf16, 4-image batch) =================
#define STAGE_BYTES 32768
#define SMEM_TOTAL  65536

__device__ __forceinline__ void load_stage(
    uint32_t sstage, const __nv_bfloat16* __restrict__ in,
    const __nv_bfloat16* __restrict__ wbf, int it, int nc, int COp, int co0,
    int pix0, int CI, int H, int W, int lgW, int lgHW, int tid)
{
    int tap = it / nc;
    int cic = it - tap * nc;
    int dy = tap / 3 - 1, dx = tap % 3 - 1;
    const __nv_bfloat16* wt = wbf + (size_t)(tap * COp + co0) * CI + (cic << 6);
    #pragma unroll
    for (int j = 0; j < 4; ++j) {
        int id = tid + (j << 8);
        int row = id >> 3, c16 = id & 7;
        uint32_t soff = SW128((row << 7) + (c16 << 4));
        cp16(sstage + 16384 + soff, wt + (size_t)row * CI + (c16 << 3), 16);
        int gp = pix0 + row;
        int img = gp >> lgHW;
        int p = gp & ((1 << lgHW) - 1);
        int y = p >> lgW, x = p & (W - 1);
        int sy = y + dy, sx = x + dx;
        const void* src = in;
        uint32_t sz = 0;
        if ((unsigned)sy < (unsigned)H && (unsigned)sx < (unsigned)W) {
            src = in + (size_t)((img << lgHW) + (sy << lgW) + sx) * CI + (cic << 6) + (c16 << 3);
            sz = 16;
        }
        cp16(sstage + soff, src, sz);
    }
    asm volatile("cp.async.commit_group;" ::: "memory");
}

__global__ void __launch_bounds__(256, 2) mma_conv_k(
    const __nv_bfloat16* __restrict__ in, const __nv_bfloat16* __restrict__ wbf,
    const float* __restrict__ bias, __nv_bfloat16* __restrict__ out,
    int CI, int COr, int COp, int H, int W, int lgW, int lgHW)
{
    extern __shared__ __align__(1024) char smem[];
    uint32_t sbase = smem_u32(smem);
    const int tid = threadIdx.x;
    const int wid = tid >> 5, lane = tid & 31;
    const int warp_m = wid & 3, warp_n = wid >> 2;
    const int co0 = blockIdx.y << 7;
    const int pix0 = blockIdx.x << 7;
    const int nc = CI >> 6;
    const int ITERS = 9 * nc;

    const uint32_t rA = (warp_m << 5) + (lane & 15);
    const uint32_t cA = (lane >> 4) << 4;
    const int t = lane >> 3;
    const uint32_t rB = (warp_n << 6) + ((t >> 1) << 3) + (lane & 7);
    const uint32_t cB = (t & 1) << 4;

    float acc[2][8][4];
    #pragma unroll
    for (int mt = 0; mt < 2; ++mt)
        #pragma unroll
        for (int nt = 0; nt < 8; ++nt)
            #pragma unroll
            for (int k = 0; k < 4; ++k) acc[mt][nt][k] = 0.f;

    load_stage(sbase, in, wbf, 0, nc, COp, co0, pix0, CI, H, W, lgW, lgHW, tid);

    for (int it = 0; it < ITERS; ++it) {
        if (it + 1 < ITERS) {
            load_stage(sbase + ((it + 1) & 1) * STAGE_BYTES, in, wbf, it + 1,
                       nc, COp, co0, pix0, CI, H, W, lgW, lgHW, tid);
            asm volatile("cp.async.wait_group 1;" ::: "memory");
        } else {
            asm volatile("cp.async.wait_group 0;" ::: "memory");
        }
        __syncthreads();

        uint32_t sA = sbase + (it & 1) * STAGE_BYTES;
        uint32_t sB = sA + 16384;
        #pragma unroll
        for (int ks = 0; ks < 4; ++ks) {
            uint32_t a[2][4];
            #pragma unroll
            for (int mt = 0; mt < 2; ++mt)
                ldx4(a[mt], sA + SW128(((rA + mt * 16) << 7) + ks * 32 + cA));
            uint32_t b[8][2];
            #pragma unroll
            for (int np = 0; np < 4; ++np) {
                uint32_t r4[4];
                ldx4(r4, sB + SW128(((rB + np * 16) << 7) + ks * 32 + cB));
                b[2 * np][0] = r4[0]; b[2 * np][1] = r4[1];
                b[2 * np + 1][0] = r4[2]; b[2 * np + 1][1] = r4[3];
            }
            #pragma unroll
            for (int mt = 0; mt < 2; ++mt)
                #pragma unroll
                for (int nt = 0; nt < 8; ++nt)
                    mma16816(acc[mt][nt], a[mt], b[nt]);
        }
        __syncthreads();
    }

    const int gid = lane >> 2, tc = lane & 3;
    #pragma unroll
    for (int nt = 0; nt < 8; ++nt) {
        int co = co0 + (warp_n << 6) + nt * 8 + tc * 2;
        if (co >= COr) continue;
        float bv0 = bias[co], bv1 = bias[co + 1];
        #pragma unroll
        for (int mt = 0; mt < 2; ++mt) {
            int pix = pix0 + (warp_m << 5) + mt * 16 + gid;
            __nv_bfloat162 h0, h1;
            h0.x = __float2bfloat16(fmaxf(acc[mt][nt][0] + bv0, 0.f));
            h0.y = __float2bfloat16(fmaxf(acc[mt][nt][1] + bv1, 0.f));
            h1.x = __float2bfloat16(fmaxf(acc[mt][nt][2] + bv0, 0.f));
            h1.y = __float2bfloat16(fmaxf(acc[mt][nt][3] + bv1, 0.f));
            *(__nv_bfloat162*)(out + (size_t)pix * COr + co) = h0;
            *(__nv_bfloat162*)(out + (size_t)(pix + 8) * COr + co) = h1;
        }
    }
}

// ================= 2x2 maxpool, NHWC bf16, 4-image batch =================
__global__ void pool_k(const __nv_bfloat16* __restrict__ in, __nv_bfloat16* __restrict__ out,
                       int C, int Ho, int Wo) {
    int idx = blockIdx.x * blockDim.x + threadIdx.x;
    int total = 4 * Ho * Wo * C;
    if (idx >= total) return;
    int c = idx % C;
    int t = idx / C;
    int x = t % Wo; t /= Wo;
    int y = t % Ho; int img = t / Ho;
    size_t base = ((size_t)(img * 2 * Ho + 2 * y) * (2 * Wo) + 2 * x) * C + c;
    size_t rstride = (size_t)(2 * Wo) * C;
    float v0 = __bfloat162float(in[base]);
    float v1 = __bfloat162float(in[base + C]);
    float v2 = __bfloat162float(in[base + rstride]);
    float v3 = __bfloat162float(in[base + rstride + C]);
    out[idx] = __float2bfloat16(fmaxf(fmaxf(v0, v1), fmaxf(v2, v3)));
}

// ================= perceptual sum of squared diffs =================
__global__ void sqdiffb_k(const __nv_bfloat16* __restrict__ a, const __nv_bfloat16* __restrict__ b) {
    float s = 0.f;
    int stride = gridDim.x * blockDim.x;
    int nv = NPERC / 8;
    for (int i = blockIdx.x * blockDim.x + threadIdx.x; i < nv; i += stride) {
        uint4 va = *(const uint4*)(a + (size_t)i * 8);
        uint4 vb = *(const uint4*)(b + (size_t)i * 8);
        const __nv_bfloat16* pa = (const __nv_bfloat16*)&va;
        const __nv_bfloat16* pb = (const __nv_bfloat16*)&vb;
        #pragma unroll
        for (int j = 0; j < 8; ++j) {
            float d = __bfloat162float(pa[j]) - __bfloat162float(pb[j]);
            s += d * d;
        }
    }
    s = block_reduce(s);
    if (threadIdx.x == 0) atomicAdd(&g_acc[6], (double)s);
}

// ================= final combine =================
__global__ void final_k(float* out) {
    double sl1  = g_acc[0] / (double)NTOT;
    double mse  = g_acc[1] / (double)NTOT;
    double mt0  = g_acc[2] / (double)CHW, mt1 = g_acc[3] / (double)CHW;
    double mp0  = g_acc[4] / (double)CHW, mp1 = g_acc[5] / (double)CHW;
    double perc = g_acc[6] / (double)NPERC;
    double hist = (2.0 - 2.0 * g_acc[7]) / 50331648.0;
    double psnr_l = 40.0 + 10.0 * log10(mse);
    double color  = 0.5 * (fabs(mt0 - mp0) + fabs(mt1 - mp1));
    out[0] = (float)(1.0 * sl1 + 0.06 * perc + 0.05 * hist + 0.0083 * psnr_l + 0.25 * color);
}

// ================= host side =================
struct LayerCfg { int woff; int CI, COr, COp, H, W, lgW, lgHW, gx, gy; };
// 4-image batch: gx = 4*H*W/128
static const LayerCfg LAY[6] = {
    {      0,  64,  64, 128, 256, 256, 8, 16, 2048, 1},
    {  73728,  64, 128, 128, 128, 128, 7, 14,  512, 1},
    { 147456, 128, 128, 128, 128, 128, 7, 14,  512, 1},
    { 294912, 128, 256, 256,  64,  64, 6, 12,  128, 2},
    { 589824, 256, 256, 256,  64,  64, 6, 12,  128, 2},
    {1179648, 256, 256, 256,  64,  64, 6, 12,  128, 2},
};

static void conv_l(int l, const __nv_bfloat16* in, const __nv_bfloat16* wbf,
                   const float* bias, __nv_bfloat16* out) {
    const LayerCfg& L = LAY[l];
    mma_conv_k<<<dim3(L.gx, L.gy), 256, SMEM_TOTAL>>>(in, wbf + L.woff, bias, out,
        L.CI, L.COr, L.COp, L.H, L.W, L.lgW, L.lgHW);
}

extern "C" void kernel_launch(void* const* d_in, const int* in_sizes, int n_in,
                              void* d_out, int out_size) {
    const float* yt = (const float*)d_in[0];
    const float* yp = (const float*)d_in[1];
    const float* W[7];
    const float* B[7];
    for (int i = 0; i < 7; ++i) {
        W[i] = (const float*)d_in[2 + 2 * i];
        B[i] = (const float*)d_in[3 + 2 * i];
    }
    __nv_bfloat16 *bufA, *bufB, *wbf;
    cudaGetSymbolAddress((void**)&bufA, g_actA);
    cudaGetSymbolAddress((void**)&bufB, g_actB);
    cudaGetSymbolAddress((void**)&wbf, g_wbf);

    cudaFuncSetAttribute(mma_conv_k, cudaFuncAttributeMaxDynamicSharedMemorySize, SMEM_TOTAL);

    init_k<<<1, 32>>>();
    loss_k<<<768, 256>>>(yt, yp);
    histmin_k<<<CHW / 256, 256>>>(yt, yp);   // reads g_S, stream-ordered after loss_k

    for (int l = 0; l < 6; ++l) {
        int total = 9 * LAY[l].COp * LAY[l].CI;
        wprep_k<<<(total + 255) / 256, 256>>>(W[l + 1], wbf + LAY[l].woff,
                                              LAY[l].COp, LAY[l].COr, LAY[l].CI);
    }

    // batched 4-image VGG chain: imgs {t0,t1,p0,p1}
    conv1_k<<<256, 256>>>(yt, yp, W[0], B[0], bufA);
    conv_l(0, bufA, wbf, B[1], bufB);
    pool_k<<<(4 * 128 * 128 * 64 + 255) / 256, 256>>>(bufB, bufA, 64, 128, 128);
    conv_l(1, bufA, wbf, B[2], bufB);
    conv_l(2, bufB, wbf, B[3], bufA);
    pool_k<<<(4 * 64 * 64 * 128 + 255) / 256, 256>>>(bufA, bufB, 128, 64, 64);
    conv_l(3, bufB, wbf, B[4], bufA);
    conv_l(4, bufA, wbf, B[5], bufB);
    conv_l(5, bufB, wbf, B[6], bufA);

    sqdiffb_k<<<1024, 256>>>(bufA, bufA + NPERC);  // true imgs vs pred imgs
    final_k<<<1, 1>>>((float*)d_out);
}